// round 5
// baseline (speedup 1.0000x reference)
#include <cuda_runtime.h>

#define S 2048
#define B 64
#define H 8
#define KK 12
#define NPOS 11
#define TBL 4096  // 1<<KK

// Scratch (__device__ globals; no allocations allowed).
__device__ unsigned long long g_tokmask[S]; // 64 token bits per row
__device__ uint4 g_AQ4[S];                  // per s: 8 x u16 = (h<<12) + addr_q
__device__ uint4 g_AK4[S];                  // per s: 8 x u16 = addr_k
__device__ uint4 g_AP4[S];                  // per rel: 8 x u16 = addr_p
__device__ uint4 g_tbw4[H * TBL / 32 / 4];  // bit table: word i, bit j = head_table[i*32+j]

// ---------------------------------------------------------------------------
// Prep: one warp per row s (ballot mask; lanes 0..7 compute per-head partial
// addresses — the three groups partition the 12 bits, so aq+ak+ap <= 4095).
// First 1024 threads also build the bit table from float4 loads.
__global__ void __launch_bounds__(256) k_prep(
        const int* __restrict__ tokens,
        const int* __restrict__ conn_heads,
        const float* __restrict__ head_table) {
    int tid = threadIdx.x;
    int lane = tid & 31;
    int gw = blockIdx.x * 8 + (tid >> 5);    // row index, 0..2047

    int t0 = tokens[gw * B + lane];
    int t1 = tokens[gw * B + 32 + lane];
    unsigned lo = __ballot_sync(0xffffffffu, t0 != 0);
    unsigned hi = __ballot_sync(0xffffffffu, t1 != 0);
    unsigned long long tm = (unsigned long long)lo | ((unsigned long long)hi << 32);
    if (lane == 0) g_tokmask[gw] = tm;

    if (lane < H) {
        int h = lane;
        int aq = 0, ak = 0, ap = 0;
#pragma unroll
        for (int j = 0; j < KK; j++) {
            int c = __ldg(&conn_heads[h * KK + j]);
            int p2 = 1 << (KK - 1 - j);
            if (c < B)          aq += (int)((tm >> c) & 1ull) * p2;
            else if (c < 2 * B) ak += (int)((tm >> (c - B)) & 1ull) * p2;
            else                ap += ((gw >> (NPOS - 1 - (c - 2 * B))) & 1) * p2;
        }
        int i = gw * 8 + h;
        ((unsigned short*)g_AQ4)[i] = (unsigned short)((h << 12) + aq);
        ((unsigned short*)g_AK4)[i] = (unsigned short)ak;
        ((unsigned short*)g_AP4)[i] = (unsigned short)ap;
    }

    int i = blockIdx.x * 256 + tid;
    if (i < H * TBL / 32) {                  // 1024 table words
        const float4* ht4 = (const float4*)head_table;
        unsigned w = 0;
#pragma unroll
        for (int r = 0; r < 8; r++) {
            float4 f = __ldg(&ht4[i * 8 + r]);
            w |= (unsigned)(f.x != 0.0f) << (r * 4);
            w |= (unsigned)(f.y != 0.0f) << (r * 4 + 1);
            w |= (unsigned)(f.z != 0.0f) << (r * 4 + 2);
            w |= (unsigned)(f.w != 0.0f) << (r * 4 + 3);
        }
        ((unsigned*)g_tbw4)[i] = w;
    }
}

// ---------------------------------------------------------------------------
// Main: TWO query rows per block (q = 2*bid+g), each scanned by an
// independent 128-thread group; 4KB bit table + conn_v staged once per block.
// Ascending 128-wide chunk scan per group, lockstep with ONE __syncthreads
// per chunk: per-warp ballots set per-group hit flags in parity-alternating
// shared slots; every thread tracks both groups' done states (hit|exhausted)
// so the loop exit is block-uniform. enc=(v<<11)|(2047-k) makes the max scan
// order-insensitive, so idle/extra chunks can never corrupt the argmax.
__global__ void __launch_bounds__(256) k_main(
        const int* __restrict__ conn_v,
        const float* __restrict__ table_v,
        float* __restrict__ out) {
    __shared__ unsigned s_tb[H * TBL / 32];   // 1024 words = 4 KB
    __shared__ int s_conn[B * KK];            // 768 ints = 3 KB
    __shared__ int s_hit[2][2];               // [parity][group]
    __shared__ int s_red[8];
    __shared__ int s_best[2];

    int tid = threadIdx.x;
    int g = tid >> 7, gtid = tid & 127;
    int q0 = blockIdx.x * 2;
    int q = q0 + g;

    // Issue all block-setup loads up front (overlap latencies).
    uint4 aq  = g_AQ4[q];
    uint4 tbw = g_tbw4[tid];
    int kc = min(gtid, q);
    uint4 ak = __ldg(&g_AK4[kc]);
    uint4 ap = __ldg(&g_AP4[q - kc]);
    int c0 = __ldg(&conn_v[tid]);
    int c1 = __ldg(&conn_v[tid + 256]);
    int c2 = __ldg(&conn_v[tid + 512]);

    ((uint4*)s_tb)[tid] = tbw;
    s_conn[tid] = c0; s_conn[tid + 256] = c1; s_conn[tid + 512] = c2;
    if (tid < 4) ((int*)s_hit)[tid] = 0;
    __syncthreads();

    int best = -1;
    bool done0 = false, done1 = false;
    int base = 0;
    for (int it = 0;; it++, base += 128) {
        bool mydone = g ? done1 : done0;
        int hitme = 0;
        if (!mydone) {
            int k = base + gtid;
            bool valid = (k <= q);
            uint4 cak = ak, cap = ap;
            if (base + 128 <= q) {             // group-uniform prefetch
                int kn = min(base + 128 + gtid, q);
                ak = __ldg(&g_AK4[kn]);
                ap = __ldg(&g_AP4[q - kn]);
            }
            // packed u16 adds: (h<<12)+(aq+ak+ap) <= 32767 per lane, no carry
            unsigned wx = cak.x + cap.x + aq.x;
            unsigned wy = cak.y + cap.y + aq.y;
            unsigned wz = cak.z + cap.z + aq.z;
            unsigned ww = cak.w + cap.w + aq.w;
            int v  = (s_tb[(wx & 0xFFFFu) >> 5] >> (wx & 31)) & 1;
            v += (s_tb[wx >> 21] >> ((wx >> 16) & 31)) & 1;
            v += (s_tb[(wy & 0xFFFFu) >> 5] >> (wy & 31)) & 1;
            v += (s_tb[wy >> 21] >> ((wy >> 16) & 31)) & 1;
            v += (s_tb[(wz & 0xFFFFu) >> 5] >> (wz & 31)) & 1;
            v += (s_tb[wz >> 21] >> ((wz >> 16) & 31)) & 1;
            v += (s_tb[(ww & 0xFFFFu) >> 5] >> (ww & 31)) & 1;
            v += (s_tb[ww >> 21] >> ((ww >> 16) & 31)) & 1;
            if (valid) best = max(best, (v << 11) | (2047 - k));
            hitme = (int)(valid && v == H);
        }
        int p = it & 1;
        unsigned bal = __ballot_sync(0xffffffffu, hitme);
        if ((tid & 31) == 0 && bal) s_hit[p][g] = 1;
        if (tid < 2) s_hit[p ^ 1][tid] = 0;    // clear next parity slot
        __syncthreads();
        int h0 = s_hit[p][0], h1 = s_hit[p][1];
        done0 = done0 || h0 || (base + 128 > q0);
        done1 = done1 || h1 || (base + 128 > q0 + 1);
        if (done0 && done1) break;
    }

    // Per-group max-reduce of encoded best (4 warps per group).
#pragma unroll
    for (int off = 16; off; off >>= 1)
        best = max(best, __shfl_xor_sync(0xffffffffu, best, off));
    if ((tid & 31) == 0) s_red[tid >> 5] = best;
    __syncthreads();
    if (gtid == 0) {
        int m = s_red[g * 4];
#pragma unroll
        for (int i = 1; i < 4; i++) m = max(m, s_red[g * 4 + i]);
        s_best[g] = m;
    }
    __syncthreads();

    if (gtid < B) {
        int m = s_best[g];
        int bv = m >> 11;
        int bk = 2047 - (m & 2047);
        float o = 0.0f;
        if (bv > 0) {
            unsigned long long msk = g_tokmask[bk];
            int addr = 0;
#pragma unroll
            for (int j = 0; j < KK; j++) {
                int c = s_conn[gtid * KK + j];
                addr += (int)((msk >> c) & 1ull) << (KK - 1 - j);
            }
            o = __ldg(&table_v[gtid * TBL + addr]);
        }
        out[q * B + gtid] = o;
    }
}

// ---------------------------------------------------------------------------
extern "C" void kernel_launch(void* const* d_in, const int* in_sizes, int n_in,
                              void* d_out, int out_size) {
    const int*   tokens     = (const int*)d_in[0];
    const int*   conn_heads = (const int*)d_in[1];
    const float* head_table = (const float*)d_in[2];
    const int*   conn_v     = (const int*)d_in[3];
    const float* table_v    = (const float*)d_in[4];
    float* out = (float*)d_out;

    k_prep<<<S / 8, 256>>>(tokens, conn_heads, head_table);
    k_main<<<S / 2, 256>>>(conn_v, table_v, out);
}